// round 8
// baseline (speedup 1.0000x reference)
#include <cuda_runtime.h>

#define B_    32768
#define W_    5
#define L_    20
#define CE_   32
#define OC_   30
#define WE_   50
#define HID_  100
#define TAGS_ 36
#define TPOS  18

#define SPB   64
#define WPB   320
#define PSTR  68
#define NT    320

typedef unsigned long long ull;

__device__ float g_Pk[3 * 100 * 32];     // [k][c][oc] (oc padded to 32, zeros)
__device__ float g_A[5 * 100 * 104];     // [w][v][j]

// ---------------- packed fp32x2 helpers ----------------
__device__ __forceinline__ ull ffma2(ull a, ull b, ull c) {
    ull d;
    asm("fma.rn.f32x2 %0, %1, %2, %3;" : "=l"(d) : "l"(a), "l"(b), "l"(c));
    return d;
}
__device__ __forceinline__ ull add2(ull a, ull b) {
    ull d;
    asm("add.rn.f32x2 %0, %1, %2;" : "=l"(d) : "l"(a), "l"(b));
    return d;
}
__device__ __forceinline__ ull pack2(float lo, float hi) {
    ull r;
    asm("mov.b64 %0, {%1, %2};"
        : "=l"(r) : "r"(__float_as_uint(lo)), "r"(__float_as_uint(hi)));
    return r;
}
__device__ __forceinline__ void unpack2(ull v, float& lo, float& hi) {
    unsigned int a, b;
    asm("mov.b64 {%0, %1}, %2;" : "=r"(a), "=r"(b) : "l"(v));
    lo = __uint_as_float(a);
    hi = __uint_as_float(b);
}

// ---------------- Kernel 0: build P and A tables ----------------
__global__ void prep_kernel(const float* __restrict__ cemb,
                            const float* __restrict__ convw,
                            const float* __restrict__ wemb,
                            const float* __restrict__ fc1w)
{
    const int idx = blockIdx.x * 256 + threadIdx.x;
    if (idx < 9600) {
        const int k  = idx / 3200;
        const int r  = idx - k * 3200;
        const int c  = r >> 5;
        const int oc = r & 31;
        float s = 0.f;
        if (oc < OC_) {
            const float* wr = convw + oc * (CE_ * 3) + k;
            const float* er = cemb + c * CE_;
            float p0 = 0.f, p1 = 0.f, p2 = 0.f, p3 = 0.f;
#pragma unroll
            for (int ce = 0; ce < CE_; ce += 4) {
                p0 = fmaf(wr[(ce + 0) * 3], er[ce + 0], p0);
                p1 = fmaf(wr[(ce + 1) * 3], er[ce + 1], p1);
                p2 = fmaf(wr[(ce + 2) * 3], er[ce + 2], p2);
                p3 = fmaf(wr[(ce + 3) * 3], er[ce + 3], p3);
            }
            s = (p0 + p1) + (p2 + p3);
        }
        g_Pk[idx] = s;
    } else {
        const int e = idx - 9600;
        if (e >= 50000) return;
        const int w = e / 10000;
        const int r = e - w * 10000;
        const int v = r / 100;
        const int j = r - v * 100;
        const float* wr = fc1w + j * 400 + w * 80;
        const float* er = wemb + v * WE_;
        float p0 = 0.f, p1 = 0.f, p2 = 0.f, p3 = 0.f;
#pragma unroll
        for (int d = 0; d < 48; d += 4) {
            p0 = fmaf(wr[d + 0], er[d + 0], p0);
            p1 = fmaf(wr[d + 1], er[d + 1], p1);
            p2 = fmaf(wr[d + 2], er[d + 2], p2);
            p3 = fmaf(wr[d + 3], er[d + 3], p3);
        }
        p0 = fmaf(wr[48], er[48], p0);
        p1 = fmaf(wr[49], er[49], p1);
        g_A[(w * 100 + v) * 104 + j] = (p0 + p1) + (p2 + p3);
    }
}

// ---------------- Kernel 1: fully fused main ----------------
__global__ __launch_bounds__(NT, 2)
void main_kernel(const int* __restrict__ inp,
                 const float* __restrict__ convb,
                 const float* __restrict__ fc1w, const float* __restrict__ fc1b,
                 const float* __restrict__ outw, const float* __restrict__ outb,
                 const float* __restrict__ wemb,
                 float* __restrict__ out)
{
    extern __shared__ __align__(16) float smem[];
    float* u0    = smem;                  // 9600: P / C double-buffer (2x 20x208) / owd
    float* poolT = smem + 9600;           // [150][68] = 10200 ; later hT[100][68]
    int*   idbuf  = (int*)(smem + 19800); // [10 warps][2][48] = 960
    int*   wid_sh = (int*)(smem + 20760); // 320
    float* b_sh   = smem + 21080;         // 104 (fc1b)
    float* cb2    = smem + 21184;         // 32  (convb)
    float* ob_sh  = smem + 21216;         // 36  (outb)

    const int tid  = threadIdx.x;
    const int warp = tid >> 5;
    const int lane = tid & 31;
    const int s0   = blockIdx.x * SPB;

    // ---- stage P + small vectors ----
    for (int i = tid; i < 9600; i += NT) u0[i] = g_Pk[i];
    if (tid < 104) b_sh[tid] = (tid < HID_) ? fc1b[tid] : 0.f;
    if (tid < 32)  cb2[tid]  = (tid < OC_) ? convb[tid] : 0.f;
    if (tid < TAGS_) ob_sh[tid] = outb[tid];
    __syncthreads();

    // ---- Phase 1: pooled conv features, software-pipelined input loads ----
    {
        const int half = lane >> 4;
        const int ocp  = lane & 15;
        const char* Pb = (const char*)u0 + ocp * 8;   // +0 / +12800 / +25600 for taps
        int* buf0 = idbuf + warp * 96;
        int* buf1 = buf0 + 48;

        // preload iter 0
        {
            const int* rp = inp + (blockIdx.x * WPB + warp * 2) * 21;
            int a = 0, b = 0;
            if (lane < 21) { a = rp[lane]; b = rp[21 + lane]; }
            if (lane < 21) { buf0[lane] = a * 128; buf0[21 + lane] = b * 128; }
            if (lane == 0) { wid_sh[warp * 2] = a; wid_sh[warp * 2 + 1] = b; }
        }
        __syncwarp();

        for (int it = 0; it < 16; ++it) {
            const int wl = it * 20 + warp * 2;
            int* cur = (it & 1) ? buf1 : buf0;
            int* nxt = (it & 1) ? buf0 : buf1;

            // issue next iteration's loads early
            int na = 0, nb = 0;
            if (it < 15) {
                const int* rp = inp + (blockIdx.x * WPB + wl + 20) * 21;
                if (lane < 21) { na = rp[lane]; nb = rp[21 + lane]; }
                if (lane == 0) { wid_sh[wl + 20] = na; wid_sh[wl + 21] = nb; }
            }

            // compute current from staged ids (pre-scaled byte offsets)
            const int* myid = cur + half * 21 + 1;
            int ca = myid[0], cb_ = myid[1];
            ull acc[TPOS];
#pragma unroll
            for (int t = 0; t < TPOS; ++t) {
                const int cc = myid[t + 2];
                const ull x0 = *(const ull*)(Pb + ca);
                const ull x1 = *(const ull*)(Pb + 12800 + cb_);
                const ull x2 = *(const ull*)(Pb + 25600 + cc);
                acc[t] = add2(add2(x0, x1), x2);
                ca = cb_; cb_ = cc;
            }

            float m0, m1;
            unpack2(acc[0], m0, m1);
#pragma unroll
            for (int t = 1; t < TPOS; ++t) {
                float x, y;
                unpack2(acc[t], x, y);
                m0 = fmaxf(m0, x);
                m1 = fmaxf(m1, y);
            }
            if (ocp < 15) {
                const int wloc = wl + half;
                const int sl   = wloc / W_;
                const int wis  = wloc - sl * W_;
                const int po   = wis * OC_ + 2 * ocp;
                poolT[po * PSTR + sl]       = m0 + cb2[2 * ocp];
                poolT[(po + 1) * PSTR + sl] = m1 + cb2[2 * ocp + 1];
            }

            // stash next ids
            if (it < 15 && lane < 21) { nxt[lane] = na * 128; nxt[21 + lane] = nb * 128; }
            __syncwarp();
        }
    }
    __syncthreads();

    // ---- Phase 2: init GEMM accs from A table ----
    const int jg = tid >> 3;
    const int sg = tid & 7;
    const int j0 = jg * 4;
    const int sb = sg * 8;
    const bool active = (tid < 200);

    ull acc[16];
    if (active) {
        const float4 bias4 = *(const float4*)&b_sh[j0];
#pragma unroll
        for (int p = 0; p < 4; ++p) {
            const int sA = sb + 2 * p;
            float4 a4 = bias4, b4 = bias4;
#pragma unroll
            for (int w = 0; w < W_; ++w) {
                const int vA = wid_sh[sA * W_ + w];
                const int vB = wid_sh[(sA + 1) * W_ + w];
                if (vA < 100) {
                    const float4 t = *(const float4*)&g_A[(w * 100 + vA) * 104 + j0];
                    a4.x += t.x; a4.y += t.y; a4.z += t.z; a4.w += t.w;
                } else {
                    const float* er = wemb + vA * WE_;
                    for (int d = 0; d < WE_; ++d) {
                        const float e = er[d];
                        a4.x += fc1w[(j0+0)*400 + w*80 + d] * e;
                        a4.y += fc1w[(j0+1)*400 + w*80 + d] * e;
                        a4.z += fc1w[(j0+2)*400 + w*80 + d] * e;
                        a4.w += fc1w[(j0+3)*400 + w*80 + d] * e;
                    }
                }
                if (vB < 100) {
                    const float4 t = *(const float4*)&g_A[(w * 100 + vB) * 104 + j0];
                    b4.x += t.x; b4.y += t.y; b4.z += t.z; b4.w += t.w;
                } else {
                    const float* er = wemb + vB * WE_;
                    for (int d = 0; d < WE_; ++d) {
                        const float e = er[d];
                        b4.x += fc1w[(j0+0)*400 + w*80 + d] * e;
                        b4.y += fc1w[(j0+1)*400 + w*80 + d] * e;
                        b4.z += fc1w[(j0+2)*400 + w*80 + d] * e;
                        b4.w += fc1w[(j0+3)*400 + w*80 + d] * e;
                    }
                }
            }
            acc[p]      = pack2(a4.x, b4.x);
            acc[4 + p]  = pack2(a4.y, b4.y);
            acc[8 + p]  = pack2(a4.z, b4.z);
            acc[12 + p] = pack2(a4.w, b4.w);
        }
    }

    // ---- Phase 3: GEMM over 8 chunks of 20 (last 10), producer/consumer split ----
    float* bufA = u0;            // 20 x 208 = 4160
    float* bufB = u0 + 4160;

    #define STAGE_CD(KB, KCNT, DST, T0, NTH)                              \
        for (int i = (T0); i < (KCNT) * HID_; i += (NTH)) {               \
            const int kk = i % (KCNT);                                    \
            const int j  = i / (KCNT);                                    \
            const int kg = (KB) + kk;                                     \
            const int w  = kg / OC_;                                      \
            const int oc = kg - w * OC_;                                  \
            const float wv = fc1w[j * 400 + w * 80 + 50 + oc];            \
            *(ull*)&(DST)[kk * 208 + 2 * j] = pack2(wv, wv);              \
        }

    STAGE_CD(0, 20, bufA, tid, NT)     // chunk 0 by all threads
    __syncthreads();

#pragma unroll
    for (int ch = 0; ch < 8; ++ch) {
        const int kb   = ch * 20;
        const int kcnt = (ch == 7) ? 10 : 20;
        float* cbuf = (ch & 1) ? bufB : bufA;
        float* nbuf = (ch & 1) ? bufA : bufB;

        if (warp < 7) {
            if (active) {
                for (int kk = 0; kk < kcnt; ++kk) {
                    const float* wrow = &cbuf[kk * 208 + 2 * j0];
                    const ulonglong2 wa  = *(const ulonglong2*)(wrow);
                    const ulonglong2 wbv = *(const ulonglong2*)(wrow + 4);
                    const float* fr = &poolT[(kb + kk) * PSTR + sb];
                    const ulonglong2 fA = *(const ulonglong2*)(fr);
                    const ulonglong2 fB = *(const ulonglong2*)(fr + 4);
                    acc[0]  = ffma2(fA.x, wa.x,  acc[0]);
                    acc[4]  = ffma2(fA.x, wa.y,  acc[4]);
                    acc[8]  = ffma2(fA.x, wbv.x, acc[8]);
                    acc[12] = ffma2(fA.x, wbv.y, acc[12]);
                    acc[1]  = ffma2(fA.y, wa.x,  acc[1]);
                    acc[5]  = ffma2(fA.y, wa.y,  acc[5]);
                    acc[9]  = ffma2(fA.y, wbv.x, acc[9]);
                    acc[13] = ffma2(fA.y, wbv.y, acc[13]);
                    acc[2]  = ffma2(fB.x, wa.x,  acc[2]);
                    acc[6]  = ffma2(fB.x, wa.y,  acc[6]);
                    acc[10] = ffma2(fB.x, wbv.x, acc[10]);
                    acc[14] = ffma2(fB.x, wbv.y, acc[14]);
                    acc[3]  = ffma2(fB.y, wa.x,  acc[3]);
                    acc[7]  = ffma2(fB.y, wa.y,  acc[7]);
                    acc[11] = ffma2(fB.y, wbv.x, acc[11]);
                    acc[15] = ffma2(fB.y, wbv.y, acc[15]);
                }
            }
        } else if (ch < 7) {
            const int nk = (ch == 6) ? 10 : 20;
            STAGE_CD(kb + 20, nk, nbuf, tid - 224, 96)
        }
        __syncthreads();
    }

    // ---- tanh -> hT[j][s] (overlays poolT); stage owd (overlays u0) ----
    float* hT = poolT;
    if (active) {
#pragma unroll
        for (int jj = 0; jj < 4; ++jj)
#pragma unroll
            for (int p = 0; p < 4; ++p) {
                float a, c;
                unpack2(acc[jj * 4 + p], a, c);
                *(ull*)&hT[(j0 + jj) * PSTR + sb + 2 * p] = pack2(tanhf(a), tanhf(c));
            }
    }
    for (int i = tid; i < TAGS_ * HID_; i += NT) {
        const int t = i / HID_;
        const int j = i - t * HID_;
        const float w = outw[i];
        u0[j * 72 + 2 * t]     = w;
        u0[j * 72 + 2 * t + 1] = w;
    }
    __syncthreads();

    // ---- Phase 4: out layer (9 of 10 warps; warp = 4 tags, lane = sample pair) ----
    if (warp < 9) {
        const int t0 = warp * 4;
        ull a4[4];
#pragma unroll
        for (int p = 0; p < 4; ++p) a4[p] = 0ull;
#pragma unroll 4
        for (int j = 0; j < HID_; ++j) {
            const ull h = *(const ull*)&hT[j * PSTR + 2 * lane];
            const float* wr = &u0[j * 72 + 2 * t0];
            const ulonglong2 w01 = *(const ulonglong2*)(wr);
            const ulonglong2 w23 = *(const ulonglong2*)(wr + 4);
            a4[0] = ffma2(h, w01.x, a4[0]);
            a4[1] = ffma2(h, w01.y, a4[1]);
            a4[2] = ffma2(h, w23.x, a4[2]);
            a4[3] = ffma2(h, w23.y, a4[3]);
        }
        float r0[4], r1[4];
#pragma unroll
        for (int tt = 0; tt < 4; ++tt) {
            float a, c;
            unpack2(a4[tt], a, c);
            const float bo = ob_sh[t0 + tt];
            r0[tt] = a + bo;
            r1[tt] = c + bo;
        }
        float* op0 = out + (s0 + 2 * lane) * TAGS_ + t0;
        *(float4*)op0           = make_float4(r0[0], r0[1], r0[2], r0[3]);
        *(float4*)(op0 + TAGS_) = make_float4(r1[0], r1[1], r1[2], r1[3]);
    }
}

// ---------------- launch ----------------
extern "C" void kernel_launch(void* const* d_in, const int* in_sizes, int n_in,
                              void* d_out, int out_size)
{
    const int*   inp   = (const int*)  d_in[0];
    const float* wemb  = (const float*)d_in[1];
    const float* cemb  = (const float*)d_in[2];
    const float* convw = (const float*)d_in[3];
    const float* convb = (const float*)d_in[4];
    const float* fc1w  = (const float*)d_in[5];
    const float* fc1b  = (const float*)d_in[6];
    const float* outw  = (const float*)d_in[7];
    const float* outb  = (const float*)d_in[8];
    float* out = (float*)d_out;

    const int smem_bytes = 21252 * 4 + 256;   // ~85.3 KB
    cudaFuncSetAttribute(main_kernel,
                         cudaFuncAttributeMaxDynamicSharedMemorySize, smem_bytes);

    prep_kernel<<<(9600 + 50000 + 255) / 256, 256>>>(cemb, convw, wemb, fc1w);
    main_kernel<<<B_ / SPB, NT, smem_bytes>>>(inp, convb, fc1w, fc1b,
                                              outw, outb, wemb, out);
}

// round 10
// speedup vs baseline: 1.2404x; 1.2404x over previous
#include <cuda_runtime.h>

#define B_    32768
#define W_    5
#define L_    20
#define CE_   32
#define OC_   30
#define WE_   50
#define HID_  100
#define TAGS_ 36
#define TPOS  18

#define SPB   64
#define WPB   320
#define PSTR  68
#define NT    320

typedef unsigned long long ull;

__device__ float g_Pk[3 * 100 * 32];     // [k][c][oc] (oc padded to 32, zeros)
__device__ float g_A[5 * 100 * 104];     // [w][v][j]

// ---------------- packed fp32x2 helpers ----------------
__device__ __forceinline__ ull ffma2(ull a, ull b, ull c) {
    ull d;
    asm("fma.rn.f32x2 %0, %1, %2, %3;" : "=l"(d) : "l"(a), "l"(b), "l"(c));
    return d;
}
__device__ __forceinline__ ull add2(ull a, ull b) {
    ull d;
    asm("add.rn.f32x2 %0, %1, %2;" : "=l"(d) : "l"(a), "l"(b));
    return d;
}
__device__ __forceinline__ ull pack2(float lo, float hi) {
    ull r;
    asm("mov.b64 %0, {%1, %2};"
        : "=l"(r) : "r"(__float_as_uint(lo)), "r"(__float_as_uint(hi)));
    return r;
}
__device__ __forceinline__ void unpack2(ull v, float& lo, float& hi) {
    unsigned int a, b;
    asm("mov.b64 {%0, %1}, %2;" : "=r"(a), "=r"(b) : "l"(v));
    lo = __uint_as_float(a);
    hi = __uint_as_float(b);
}

// ---------------- Kernel 0: build P and A tables ----------------
__global__ void prep_kernel(const float* __restrict__ cemb,
                            const float* __restrict__ convw,
                            const float* __restrict__ wemb,
                            const float* __restrict__ fc1w)
{
    const int idx = blockIdx.x * 256 + threadIdx.x;
    if (idx < 9600) {
        const int k  = idx / 3200;
        const int r  = idx - k * 3200;
        const int c  = r >> 5;
        const int oc = r & 31;
        float s = 0.f;
        if (oc < OC_) {
            const float* wr = convw + oc * (CE_ * 3) + k;
            const float* er = cemb + c * CE_;
            float p0 = 0.f, p1 = 0.f, p2 = 0.f, p3 = 0.f;
#pragma unroll
            for (int ce = 0; ce < CE_; ce += 4) {
                p0 = fmaf(wr[(ce + 0) * 3], er[ce + 0], p0);
                p1 = fmaf(wr[(ce + 1) * 3], er[ce + 1], p1);
                p2 = fmaf(wr[(ce + 2) * 3], er[ce + 2], p2);
                p3 = fmaf(wr[(ce + 3) * 3], er[ce + 3], p3);
            }
            s = (p0 + p1) + (p2 + p3);
        }
        g_Pk[idx] = s;
    } else {
        const int e = idx - 9600;
        if (e >= 50000) return;
        const int w = e / 10000;
        const int r = e - w * 10000;
        const int v = r / 100;
        const int j = r - v * 100;
        const float* wr = fc1w + j * 400 + w * 80;
        const float* er = wemb + v * WE_;
        float p0 = 0.f, p1 = 0.f, p2 = 0.f, p3 = 0.f;
#pragma unroll
        for (int d = 0; d < 48; d += 4) {
            p0 = fmaf(wr[d + 0], er[d + 0], p0);
            p1 = fmaf(wr[d + 1], er[d + 1], p1);
            p2 = fmaf(wr[d + 2], er[d + 2], p2);
            p3 = fmaf(wr[d + 3], er[d + 3], p3);
        }
        p0 = fmaf(wr[48], er[48], p0);
        p1 = fmaf(wr[49], er[49], p1);
        g_A[(w * 100 + v) * 104 + j] = (p0 + p1) + (p2 + p3);
    }
}

// ---------------- Kernel 1: fully fused main ----------------
__global__ __launch_bounds__(NT, 2)
void main_kernel(const int* __restrict__ inp,
                 const float* __restrict__ convb,
                 const float* __restrict__ fc1w, const float* __restrict__ fc1b,
                 const float* __restrict__ outw, const float* __restrict__ outb,
                 const float* __restrict__ wemb,
                 float* __restrict__ out)
{
    extern __shared__ __align__(16) float smem[];
    float* u0    = smem;                  // 15600: P(9600) -> C[150][104] -> owd(7200)
    float* poolT = smem + 15600;          // [150][68] = 10200 ; later hT[100][68]
    int*   idbuf  = (int*)(smem + 25800); // [10 warps][2][48] = 960
    int*   wid_sh = (int*)(smem + 26760); // 320
    float* b_sh   = smem + 27080;         // 104 (fc1b)
    float* cb2    = smem + 27184;         // 32  (convb)
    float* ob_sh  = smem + 27216;         // 36  (outb)

    const int tid  = threadIdx.x;
    const int warp = tid >> 5;
    const int lane = tid & 31;
    const int s0   = blockIdx.x * SPB;

    // ---- stage P + small vectors ----
    for (int i = tid; i < 9600; i += NT) u0[i] = g_Pk[i];
    if (tid < 104) b_sh[tid] = (tid < HID_) ? fc1b[tid] : 0.f;
    if (tid < 32)  cb2[tid]  = (tid < OC_) ? convb[tid] : 0.f;
    if (tid < TAGS_) ob_sh[tid] = outb[tid];
    __syncthreads();

    // ---- Phase 1: pooled conv features, software-pipelined input loads ----
    {
        const int half = lane >> 4;
        const int ocp  = lane & 15;
        const char* Pb = (const char*)u0 + ocp * 8;   // +0 / +12800 / +25600 taps
        int* buf0 = idbuf + warp * 96;
        int* buf1 = buf0 + 48;

        {
            const int* rp = inp + (blockIdx.x * WPB + warp * 2) * 21;
            int a = 0, b = 0;
            if (lane < 21) { a = rp[lane]; b = rp[21 + lane]; }
            if (lane < 21) { buf0[lane] = a * 128; buf0[21 + lane] = b * 128; }
            if (lane == 0) { wid_sh[warp * 2] = a; wid_sh[warp * 2 + 1] = b; }
        }
        __syncwarp();

        for (int it = 0; it < 16; ++it) {
            const int wl = it * 20 + warp * 2;
            int* cur = (it & 1) ? buf1 : buf0;
            int* nxt = (it & 1) ? buf0 : buf1;

            int na = 0, nb = 0;
            if (it < 15) {
                const int* rp = inp + (blockIdx.x * WPB + wl + 20) * 21;
                if (lane < 21) { na = rp[lane]; nb = rp[21 + lane]; }
                if (lane == 0) { wid_sh[wl + 20] = na; wid_sh[wl + 21] = nb; }
            }

            const int* myid = cur + half * 21 + 1;
            int ca = myid[0], cb_ = myid[1];
            ull acc[TPOS];
#pragma unroll
            for (int t = 0; t < TPOS; ++t) {
                const int cc = myid[t + 2];
                const ull x0 = *(const ull*)(Pb + ca);
                const ull x1 = *(const ull*)(Pb + 12800 + cb_);
                const ull x2 = *(const ull*)(Pb + 25600 + cc);
                acc[t] = add2(add2(x0, x1), x2);
                ca = cb_; cb_ = cc;
            }

            float m0, m1;
            unpack2(acc[0], m0, m1);
#pragma unroll
            for (int t = 1; t < TPOS; ++t) {
                float x, y;
                unpack2(acc[t], x, y);
                m0 = fmaxf(m0, x);
                m1 = fmaxf(m1, y);
            }
            if (ocp < 15) {
                const int wloc = wl + half;
                const int sl   = wloc / W_;
                const int wis  = wloc - sl * W_;
                const int po   = wis * OC_ + 2 * ocp;
                poolT[po * PSTR + sl]       = m0 + cb2[2 * ocp];
                poolT[(po + 1) * PSTR + sl] = m1 + cb2[2 * ocp + 1];
            }

            if (it < 15 && lane < 21) { nxt[lane] = na * 128; nxt[21 + lane] = nb * 128; }
            __syncwarp();
        }
    }
    __syncthreads();   // P no longer needed; u0 becomes C

    // ---- Phase 2a: stage FULL C = fc1w conv-half [k=150][j=100] into u0 ----
    float* csh = u0;   // [k][104]
    for (int i = tid; i < 150 * HID_; i += NT) {
        const int kk = i % 150;
        const int j  = i / 150;
        const int w  = kk / OC_;
        const int oc = kk - w * OC_;
        csh[kk * 104 + j] = fc1w[j * 400 + w * 80 + 50 + oc];
    }

    // ---- Phase 2b: init GEMM accumulators from A table (overlaps staging LDGs) ----
    const int jg = tid >> 3;
    const int sg = tid & 7;
    const int j0 = jg * 4;
    const int sb = sg * 8;
    const bool active = (tid < 200);

    ull acc[16];
    if (active) {
        const float4 bias4 = *(const float4*)&b_sh[j0];
#pragma unroll
        for (int p = 0; p < 4; ++p) {
            const int sA = sb + 2 * p;
            float4 a4 = bias4, b4 = bias4;
#pragma unroll
            for (int w = 0; w < W_; ++w) {
                const int vA = wid_sh[sA * W_ + w];
                const int vB = wid_sh[(sA + 1) * W_ + w];
                if (vA < 100) {
                    const float4 t = *(const float4*)&g_A[(w * 100 + vA) * 104 + j0];
                    a4.x += t.x; a4.y += t.y; a4.z += t.z; a4.w += t.w;
                } else {
                    const float* er = wemb + vA * WE_;
                    for (int d = 0; d < WE_; ++d) {
                        const float e = er[d];
                        a4.x += fc1w[(j0+0)*400 + w*80 + d] * e;
                        a4.y += fc1w[(j0+1)*400 + w*80 + d] * e;
                        a4.z += fc1w[(j0+2)*400 + w*80 + d] * e;
                        a4.w += fc1w[(j0+3)*400 + w*80 + d] * e;
                    }
                }
                if (vB < 100) {
                    const float4 t = *(const float4*)&g_A[(w * 100 + vB) * 104 + j0];
                    b4.x += t.x; b4.y += t.y; b4.z += t.z; b4.w += t.w;
                } else {
                    const float* er = wemb + vB * WE_;
                    for (int d = 0; d < WE_; ++d) {
                        const float e = er[d];
                        b4.x += fc1w[(j0+0)*400 + w*80 + d] * e;
                        b4.y += fc1w[(j0+1)*400 + w*80 + d] * e;
                        b4.z += fc1w[(j0+2)*400 + w*80 + d] * e;
                        b4.w += fc1w[(j0+3)*400 + w*80 + d] * e;
                    }
                }
            }
            acc[p]      = pack2(a4.x, b4.x);
            acc[4 + p]  = pack2(a4.y, b4.y);
            acc[8 + p]  = pack2(a4.z, b4.z);
            acc[12 + p] = pack2(a4.w, b4.w);
        }
    }
    __syncthreads();

    // ---- Phase 3: GEMM, all 150 k, ZERO barriers ----
    if (active) {
#pragma unroll 5
        for (int kk = 0; kk < 150; ++kk) {
            const float4 wq = *(const float4*)&csh[kk * 104 + j0];
            const float* fr = &poolT[kk * PSTR + sb];
            const ulonglong2 fA = *(const ulonglong2*)(fr);
            const ulonglong2 fB = *(const ulonglong2*)(fr + 4);
            const ull w0 = pack2(wq.x, wq.x);
            const ull w1 = pack2(wq.y, wq.y);
            const ull w2 = pack2(wq.z, wq.z);
            const ull w3 = pack2(wq.w, wq.w);
            acc[0]  = ffma2(fA.x, w0, acc[0]);
            acc[4]  = ffma2(fA.x, w1, acc[4]);
            acc[8]  = ffma2(fA.x, w2, acc[8]);
            acc[12] = ffma2(fA.x, w3, acc[12]);
            acc[1]  = ffma2(fA.y, w0, acc[1]);
            acc[5]  = ffma2(fA.y, w1, acc[5]);
            acc[9]  = ffma2(fA.y, w2, acc[9]);
            acc[13] = ffma2(fA.y, w3, acc[13]);
            acc[2]  = ffma2(fB.x, w0, acc[2]);
            acc[6]  = ffma2(fB.x, w1, acc[6]);
            acc[10] = ffma2(fB.x, w2, acc[10]);
            acc[14] = ffma2(fB.x, w3, acc[14]);
            acc[3]  = ffma2(fB.y, w0, acc[3]);
            acc[7]  = ffma2(fB.y, w1, acc[7]);
            acc[11] = ffma2(fB.y, w2, acc[11]);
            acc[15] = ffma2(fB.y, w3, acc[15]);
        }
    }
    __syncthreads();   // C reads + pool reads done

    // ---- tanh -> hT[j][s] (overlays poolT); stage owd (overlays u0) ----
    float* hT = poolT;
    if (active) {
#pragma unroll
        for (int jj = 0; jj < 4; ++jj)
#pragma unroll
            for (int p = 0; p < 4; ++p) {
                float a, c;
                unpack2(acc[jj * 4 + p], a, c);
                *(ull*)&hT[(j0 + jj) * PSTR + sb + 2 * p] = pack2(tanhf(a), tanhf(c));
            }
    }
    for (int i = tid; i < TAGS_ * HID_; i += NT) {
        const int t = i / HID_;
        const int j = i - t * HID_;
        const float w = outw[i];
        u0[j * 72 + 2 * t]     = w;
        u0[j * 72 + 2 * t + 1] = w;
    }
    __syncthreads();

    // ---- Phase 4: out layer (9 of 10 warps; warp = 4 tags, lane = sample pair) ----
    if (warp < 9) {
        const int t0 = warp * 4;
        ull a4[4];
#pragma unroll
        for (int p = 0; p < 4; ++p) a4[p] = 0ull;
#pragma unroll 4
        for (int j = 0; j < HID_; ++j) {
            const ull h = *(const ull*)&hT[j * PSTR + 2 * lane];
            const float* wr = &u0[j * 72 + 2 * t0];
            const ulonglong2 w01 = *(const ulonglong2*)(wr);
            const ulonglong2 w23 = *(const ulonglong2*)(wr + 4);
            a4[0] = ffma2(h, w01.x, a4[0]);
            a4[1] = ffma2(h, w01.y, a4[1]);
            a4[2] = ffma2(h, w23.x, a4[2]);
            a4[3] = ffma2(h, w23.y, a4[3]);
        }
        float r0[4], r1[4];
#pragma unroll
        for (int tt = 0; tt < 4; ++tt) {
            float a, c;
            unpack2(a4[tt], a, c);
            const float bo = ob_sh[t0 + tt];
            r0[tt] = a + bo;
            r1[tt] = c + bo;
        }
        float* op0 = out + (s0 + 2 * lane) * TAGS_ + t0;
        *(float4*)op0           = make_float4(r0[0], r0[1], r0[2], r0[3]);
        *(float4*)(op0 + TAGS_) = make_float4(r1[0], r1[1], r1[2], r1[3]);
    }
}

// ---------------- launch ----------------
extern "C" void kernel_launch(void* const* d_in, const int* in_sizes, int n_in,
                              void* d_out, int out_size)
{
    const int*   inp   = (const int*)  d_in[0];
    const float* wemb  = (const float*)d_in[1];
    const float* cemb  = (const float*)d_in[2];
    const float* convw = (const float*)d_in[3];
    const float* convb = (const float*)d_in[4];
    const float* fc1w  = (const float*)d_in[5];
    const float* fc1b  = (const float*)d_in[6];
    const float* outw  = (const float*)d_in[7];
    const float* outb  = (const float*)d_in[8];
    float* out = (float*)d_out;

    const int smem_bytes = 27252 * 4 + 256;   // ~106.7 KB
    cudaFuncSetAttribute(main_kernel,
                         cudaFuncAttributeMaxDynamicSharedMemorySize, smem_bytes);

    prep_kernel<<<(9600 + 50000 + 255) / 256, 256>>>(cemb, convw, wemb, fc1w);
    main_kernel<<<B_ / SPB, NT, smem_bytes>>>(inp, convb, fc1w, fc1b,
                                              outw, outb, wemb, out);
}

// round 12
// speedup vs baseline: 1.3282x; 1.0708x over previous
#include <cuda_runtime.h>

#define B_    32768
#define W_    5
#define L_    20
#define CE_   32
#define OC_   30
#define WE_   50
#define HID_  100
#define TAGS_ 36
#define TPOS  18

#define SPB   64
#define WPB   320
#define PSTR  68
#define NT    320

typedef unsigned long long ull;

__device__ float g_Pk[3 * 100 * 32];     // [k][c][oc] (oc padded to 32, zeros)
__device__ float g_A[5 * 100 * 104];     // [w][v][j]
__device__ float g_C[150 * 104];         // [k][j] transposed fc1w conv-half (row 416B)

// ---------------- packed fp32x2 helpers ----------------
__device__ __forceinline__ ull ffma2(ull a, ull b, ull c) {
    ull d;
    asm("fma.rn.f32x2 %0, %1, %2, %3;" : "=l"(d) : "l"(a), "l"(b), "l"(c));
    return d;
}
__device__ __forceinline__ ull add2(ull a, ull b) {
    ull d;
    asm("add.rn.f32x2 %0, %1, %2;" : "=l"(d) : "l"(a), "l"(b));
    return d;
}
__device__ __forceinline__ ull pack2(float lo, float hi) {
    ull r;
    asm("mov.b64 %0, {%1, %2};"
        : "=l"(r) : "r"(__float_as_uint(lo)), "r"(__float_as_uint(hi)));
    return r;
}
__device__ __forceinline__ void unpack2(ull v, float& lo, float& hi) {
    unsigned int a, b;
    asm("mov.b64 {%0, %1}, %2;" : "=r"(a), "=r"(b) : "l"(v));
    lo = __uint_as_float(a);
    hi = __uint_as_float(b);
}

// ---------------- Kernel 0: build P, A, C tables ----------------
__global__ void prep_kernel(const float* __restrict__ cemb,
                            const float* __restrict__ convw,
                            const float* __restrict__ wemb,
                            const float* __restrict__ fc1w)
{
    const int idx = blockIdx.x * 256 + threadIdx.x;
    if (idx < 9600) {
        const int k  = idx / 3200;
        const int r  = idx - k * 3200;
        const int c  = r >> 5;
        const int oc = r & 31;
        float s = 0.f;
        if (oc < OC_) {
            const float* wr = convw + oc * (CE_ * 3) + k;
            const float* er = cemb + c * CE_;
            float p0 = 0.f, p1 = 0.f, p2 = 0.f, p3 = 0.f;
#pragma unroll
            for (int ce = 0; ce < CE_; ce += 4) {
                p0 = fmaf(wr[(ce + 0) * 3], er[ce + 0], p0);
                p1 = fmaf(wr[(ce + 1) * 3], er[ce + 1], p1);
                p2 = fmaf(wr[(ce + 2) * 3], er[ce + 2], p2);
                p3 = fmaf(wr[(ce + 3) * 3], er[ce + 3], p3);
            }
            s = (p0 + p1) + (p2 + p3);
        }
        g_Pk[idx] = s;
    } else if (idx < 59600) {
        const int e = idx - 9600;
        const int w = e / 10000;
        const int r = e - w * 10000;
        const int v = r / 100;
        const int j = r - v * 100;
        const float* wr = fc1w + j * 400 + w * 80;
        const float* er = wemb + v * WE_;
        float p0 = 0.f, p1 = 0.f, p2 = 0.f, p3 = 0.f;
#pragma unroll
        for (int d = 0; d < 48; d += 4) {
            p0 = fmaf(wr[d + 0], er[d + 0], p0);
            p1 = fmaf(wr[d + 1], er[d + 1], p1);
            p2 = fmaf(wr[d + 2], er[d + 2], p2);
            p3 = fmaf(wr[d + 3], er[d + 3], p3);
        }
        p0 = fmaf(wr[48], er[48], p0);
        p1 = fmaf(wr[49], er[49], p1);
        g_A[(w * 100 + v) * 104 + j] = (p0 + p1) + (p2 + p3);
    } else {
        const int e = idx - 59600;
        if (e >= 150 * HID_) return;
        const int j  = e / 150;
        const int kk = e - j * 150;
        const int w  = kk / OC_;
        const int oc = kk - w * OC_;
        g_C[kk * 104 + j] = fc1w[j * 400 + w * 80 + 50 + oc];
    }
}

// ---------------- Kernel 1: fully fused main ----------------
__global__ __launch_bounds__(NT, 2)
void main_kernel(const int* __restrict__ inp,
                 const float* __restrict__ convb,
                 const float* __restrict__ fc1w, const float* __restrict__ fc1b,
                 const float* __restrict__ outw, const float* __restrict__ outb,
                 const float* __restrict__ wemb,
                 float* __restrict__ out)
{
    extern __shared__ __align__(16) float smem[];
    float* u0    = smem;                  // 9600: P, later owd (7200)
    float* poolT = smem + 9600;           // [150][68] = 10200 ; later hT[100][68]
    int*   idbuf  = (int*)(smem + 19800); // [10 warps][2][48] = 960
    int*   wid_sh = (int*)(smem + 20760); // 320
    float* b_sh   = smem + 21080;         // 104 (fc1b)
    float* cb2    = smem + 21184;         // 32  (convb)
    float* ob_sh  = smem + 21216;         // 36  (outb)

    const int tid  = threadIdx.x;
    const int warp = tid >> 5;
    const int lane = tid & 31;
    const int s0   = blockIdx.x * SPB;

    // ---- stage P + small vectors ----
    for (int i = tid; i < 9600; i += NT) u0[i] = g_Pk[i];
    if (tid < 104) b_sh[tid] = (tid < HID_) ? fc1b[tid] : 0.f;
    if (tid < 32)  cb2[tid]  = (tid < OC_) ? convb[tid] : 0.f;
    if (tid < TAGS_) ob_sh[tid] = outb[tid];
    __syncthreads();

    // ---- Phase 1: pooled conv features, software-pipelined input loads ----
    {
        const int half = lane >> 4;
        const int ocp  = lane & 15;
        const char* Pb = (const char*)u0 + ocp * 8;   // +0 / +12800 / +25600 taps
        int* buf0 = idbuf + warp * 96;
        int* buf1 = buf0 + 48;

        {
            const int* rp = inp + (blockIdx.x * WPB + warp * 2) * 21;
            int a = 0, b = 0;
            if (lane < 21) { a = rp[lane]; b = rp[21 + lane]; }
            if (lane < 21) { buf0[lane] = a * 128; buf0[21 + lane] = b * 128; }
            if (lane == 0) { wid_sh[warp * 2] = a; wid_sh[warp * 2 + 1] = b; }
        }
        __syncwarp();

        for (int it = 0; it < 16; ++it) {
            const int wl = it * 20 + warp * 2;
            int* cur = (it & 1) ? buf1 : buf0;
            int* nxt = (it & 1) ? buf0 : buf1;

            int na = 0, nb = 0;
            if (it < 15) {
                const int* rp = inp + (blockIdx.x * WPB + wl + 20) * 21;
                if (lane < 21) { na = rp[lane]; nb = rp[21 + lane]; }
                if (lane == 0) { wid_sh[wl + 20] = na; wid_sh[wl + 21] = nb; }
            }

            const int* myid = cur + half * 21 + 1;
            int ca = myid[0], cb_ = myid[1];
            ull acc[TPOS];
#pragma unroll
            for (int t = 0; t < TPOS; ++t) {
                const int cc = myid[t + 2];
                const ull x0 = *(const ull*)(Pb + ca);
                const ull x1 = *(const ull*)(Pb + 12800 + cb_);
                const ull x2 = *(const ull*)(Pb + 25600 + cc);
                acc[t] = add2(add2(x0, x1), x2);
                ca = cb_; cb_ = cc;
            }

            float m0, m1;
            unpack2(acc[0], m0, m1);
#pragma unroll
            for (int t = 1; t < TPOS; ++t) {
                float x, y;
                unpack2(acc[t], x, y);
                m0 = fmaxf(m0, x);
                m1 = fmaxf(m1, y);
            }
            if (ocp < 15) {
                const int wloc = wl + half;
                const int sl   = wloc / W_;
                const int wis  = wloc - sl * W_;
                const int po   = wis * OC_ + 2 * ocp;
                poolT[po * PSTR + sl]       = m0 + cb2[2 * ocp];
                poolT[(po + 1) * PSTR + sl] = m1 + cb2[2 * ocp + 1];
            }

            if (it < 15 && lane < 21) { nxt[lane] = na * 128; nxt[21 + lane] = nb * 128; }
            __syncwarp();
        }
    }
    __syncthreads();   // P dead; u0 free for owd

    // ---- stage owd early (LDGs overlap Phase 2/3 compute) ----
    for (int i = tid; i < TAGS_ * HID_; i += NT) {
        const int t = i / HID_;
        const int j = i - t * HID_;
        const float w = outw[i];
        u0[j * 72 + 2 * t]     = w;
        u0[j * 72 + 2 * t + 1] = w;
    }

    // ---- Phase 2: init GEMM accumulators from A table ----
    const int jg = tid >> 3;
    const int sg = tid & 7;
    const int j0 = jg * 4;
    const int sb = sg * 8;
    const bool active = (tid < 200);

    ull acc[16];
    if (active) {
        const float4 bias4 = *(const float4*)&b_sh[j0];
#pragma unroll
        for (int p = 0; p < 4; ++p) {
            const int sA = sb + 2 * p;
            float4 a4 = bias4, b4 = bias4;
#pragma unroll
            for (int w = 0; w < W_; ++w) {
                const int vA = wid_sh[sA * W_ + w];
                const int vB = wid_sh[(sA + 1) * W_ + w];
                if (vA < 100) {
                    const float4 t = *(const float4*)&g_A[(w * 100 + vA) * 104 + j0];
                    a4.x += t.x; a4.y += t.y; a4.z += t.z; a4.w += t.w;
                } else {
                    const float* er = wemb + vA * WE_;
                    for (int d = 0; d < WE_; ++d) {
                        const float e = er[d];
                        a4.x += fc1w[(j0+0)*400 + w*80 + d] * e;
                        a4.y += fc1w[(j0+1)*400 + w*80 + d] * e;
                        a4.z += fc1w[(j0+2)*400 + w*80 + d] * e;
                        a4.w += fc1w[(j0+3)*400 + w*80 + d] * e;
                    }
                }
                if (vB < 100) {
                    const float4 t = *(const float4*)&g_A[(w * 100 + vB) * 104 + j0];
                    b4.x += t.x; b4.y += t.y; b4.z += t.z; b4.w += t.w;
                } else {
                    const float* er = wemb + vB * WE_;
                    for (int d = 0; d < WE_; ++d) {
                        const float e = er[d];
                        b4.x += fc1w[(j0+0)*400 + w*80 + d] * e;
                        b4.y += fc1w[(j0+1)*400 + w*80 + d] * e;
                        b4.z += fc1w[(j0+2)*400 + w*80 + d] * e;
                        b4.w += fc1w[(j0+3)*400 + w*80 + d] * e;
                    }
                }
            }
            acc[p]      = pack2(a4.x, b4.x);
            acc[4 + p]  = pack2(a4.y, b4.y);
            acc[8 + p]  = pack2(a4.z, b4.z);
            acc[12 + p] = pack2(a4.w, b4.w);
        }
    }

    // ---- Phase 3: GEMM, C read via broadcast LDG.128 from g_C (L1/L2-hot) ----
    if (active) {
        const float* cbase = g_C + j0;
#pragma unroll 5
        for (int kk = 0; kk < 150; ++kk) {
            const float4 wq = *(const float4*)(cbase + kk * 104);
            const float* fr = &poolT[kk * PSTR + sb];
            const ulonglong2 fA = *(const ulonglong2*)(fr);
            const ulonglong2 fB = *(const ulonglong2*)(fr + 4);
            const ull w0 = pack2(wq.x, wq.x);
            const ull w1 = pack2(wq.y, wq.y);
            const ull w2 = pack2(wq.z, wq.z);
            const ull w3 = pack2(wq.w, wq.w);
            acc[0]  = ffma2(fA.x, w0, acc[0]);
            acc[4]  = ffma2(fA.x, w1, acc[4]);
            acc[8]  = ffma2(fA.x, w2, acc[8]);
            acc[12] = ffma2(fA.x, w3, acc[12]);
            acc[1]  = ffma2(fA.y, w0, acc[1]);
            acc[5]  = ffma2(fA.y, w1, acc[5]);
            acc[9]  = ffma2(fA.y, w2, acc[9]);
            acc[13] = ffma2(fA.y, w3, acc[13]);
            acc[2]  = ffma2(fB.x, w0, acc[2]);
            acc[6]  = ffma2(fB.x, w1, acc[6]);
            acc[10] = ffma2(fB.x, w2, acc[10]);
            acc[14] = ffma2(fB.x, w3, acc[14]);
            acc[3]  = ffma2(fB.y, w0, acc[3]);
            acc[7]  = ffma2(fB.y, w1, acc[7]);
            acc[11] = ffma2(fB.y, w2, acc[11]);
            acc[15] = ffma2(fB.y, w3, acc[15]);
        }
    }
    __syncthreads();   // pool reads done before hT overlay

    // ---- tanh -> hT[j][s] (overlays poolT) ----
    float* hT = poolT;
    if (active) {
#pragma unroll
        for (int jj = 0; jj < 4; ++jj)
#pragma unroll
            for (int p = 0; p < 4; ++p) {
                float a, c;
                unpack2(acc[jj * 4 + p], a, c);
                *(ull*)&hT[(j0 + jj) * PSTR + sb + 2 * p] = pack2(tanhf(a), tanhf(c));
            }
    }
    __syncthreads();

    // ---- Phase 4: out layer (9 of 10 warps; warp = 4 tags, lane = sample pair) ----
    if (warp < 9) {
        const int t0 = warp * 4;
        ull a4[4];
#pragma unroll
        for (int p = 0; p < 4; ++p) a4[p] = 0ull;
#pragma unroll 4
        for (int j = 0; j < HID_; ++j) {
            const ull h = *(const ull*)&hT[j * PSTR + 2 * lane];
            const float* wr = &u0[j * 72 + 2 * t0];
            const ulonglong2 w01 = *(const ulonglong2*)(wr);
            const ulonglong2 w23 = *(const ulonglong2*)(wr + 4);
            a4[0] = ffma2(h, w01.x, a4[0]);
            a4[1] = ffma2(h, w01.y, a4[1]);
            a4[2] = ffma2(h, w23.x, a4[2]);
            a4[3] = ffma2(h, w23.y, a4[3]);
        }
        float r0[4], r1[4];
#pragma unroll
        for (int tt = 0; tt < 4; ++tt) {
            float a, c;
            unpack2(a4[tt], a, c);
            const float bo = ob_sh[t0 + tt];
            r0[tt] = a + bo;
            r1[tt] = c + bo;
        }
        float* op0 = out + (s0 + 2 * lane) * TAGS_ + t0;
        *(float4*)op0           = make_float4(r0[0], r0[1], r0[2], r0[3]);
        *(float4*)(op0 + TAGS_) = make_float4(r1[0], r1[1], r1[2], r1[3]);
    }
}

// ---------------- launch ----------------
extern "C" void kernel_launch(void* const* d_in, const int* in_sizes, int n_in,
                              void* d_out, int out_size)
{
    const int*   inp   = (const int*)  d_in[0];
    const float* wemb  = (const float*)d_in[1];
    const float* cemb  = (const float*)d_in[2];
    const float* convw = (const float*)d_in[3];
    const float* convb = (const float*)d_in[4];
    const float* fc1w  = (const float*)d_in[5];
    const float* fc1b  = (const float*)d_in[6];
    const float* outw  = (const float*)d_in[7];
    const float* outb  = (const float*)d_in[8];
    float* out = (float*)d_out;

    const int smem_bytes = 21252 * 4 + 256;   // ~85.3 KB
    cudaFuncSetAttribute(main_kernel,
                         cudaFuncAttributeMaxDynamicSharedMemorySize, smem_bytes);

    prep_kernel<<<(9600 + 50000 + 15000 + 255) / 256, 256>>>(cemb, convw, wemb, fc1w);
    main_kernel<<<B_ / SPB, NT, smem_bytes>>>(inp, convb, fc1w, fc1b,
                                              outw, outb, wemb, out);
}